// round 1
// baseline (speedup 1.0000x reference)
#include <cuda_runtime.h>

// MatchingLoss: B=64 batches, N=100000 points, 2D.
// loss = 1000 * mean_b f( (mean||proj-img|| - mean||org-img||) / 1440 )
//   f(d) = ((1 + 5*relu(-d))*d + 5*relu(d)) / (1 + |d|)

#define BATCH   64
#define NPTS    100000
#define N4      (NPTS / 2)      // 50000 float4 per batch (2 points per float4)
#define CHUNKS  16
#define THREADS 256
#define DENOM   1440.0f

__device__ float g_sum[2 * BATCH];   // [0..63]: proj-img sums, [64..127]: org-img sums

__global__ void zero_kernel() {
    int i = threadIdx.x;
    if (i < 2 * BATCH) g_sum[i] = 0.0f;
}

__global__ __launch_bounds__(THREADS) void reduce_kernel(
    const float4* __restrict__ img,
    const float4* __restrict__ proj,
    const float4* __restrict__ org)
{
    const int b     = blockIdx.x / CHUNKS;
    const int chunk = blockIdx.x % CHUNKS;
    const int per   = N4 / CHUNKS;            // 3125, exact
    const int start = chunk * per;
    const int end   = start + per;

    const float4* ib = img  + (size_t)b * N4;
    const float4* pb = proj + (size_t)b * N4;
    const float4* ob = org  + (size_t)b * N4;

    float s1 = 0.0f, s2 = 0.0f;
    for (int i = start + threadIdx.x; i < end; i += THREADS) {
        float4 a = ib[i];
        float4 p = pb[i];
        float4 o = ob[i];
        float dx, dy;
        dx = p.x - a.x; dy = p.y - a.y; s1 += sqrtf(dx * dx + dy * dy);
        dx = p.z - a.z; dy = p.w - a.w; s1 += sqrtf(dx * dx + dy * dy);
        dx = o.x - a.x; dy = o.y - a.y; s2 += sqrtf(dx * dx + dy * dy);
        dx = o.z - a.z; dy = o.w - a.w; s2 += sqrtf(dx * dx + dy * dy);
    }

    // warp reduce
    #pragma unroll
    for (int off = 16; off > 0; off >>= 1) {
        s1 += __shfl_down_sync(0xFFFFFFFFu, s1, off);
        s2 += __shfl_down_sync(0xFFFFFFFFu, s2, off);
    }

    __shared__ float sh1[THREADS / 32];
    __shared__ float sh2[THREADS / 32];
    int lane = threadIdx.x & 31;
    int wid  = threadIdx.x >> 5;
    if (lane == 0) { sh1[wid] = s1; sh2[wid] = s2; }
    __syncthreads();

    if (wid == 0) {
        s1 = (lane < THREADS / 32) ? sh1[lane] : 0.0f;
        s2 = (lane < THREADS / 32) ? sh2[lane] : 0.0f;
        #pragma unroll
        for (int off = 4; off > 0; off >>= 1) {
            s1 += __shfl_down_sync(0xFFFFFFFFu, s1, off);
            s2 += __shfl_down_sync(0xFFFFFFFFu, s2, off);
        }
        if (lane == 0) {
            atomicAdd(&g_sum[b], s1);
            atomicAdd(&g_sum[BATCH + b], s2);
        }
    }
}

__global__ void final_kernel(float* __restrict__ out) {
    __shared__ float sh[BATCH];
    int b = threadIdx.x;
    const float inv = 1.0f / ((float)NPTS * DENOM);
    float d = (g_sum[b] - g_sum[BATCH + b]) * inv;
    float reward  = (1.0f + 5.0f * fmaxf(-d, 0.0f)) * d;
    float penalty = 5.0f * fmaxf(d, 0.0f);
    sh[b] = (reward + penalty) / (1.0f + fabsf(d));
    __syncthreads();
    if (b == 0) {
        float t = 0.0f;
        #pragma unroll
        for (int i = 0; i < BATCH; i++) t += sh[i];
        out[0] = 1000.0f * t / (float)BATCH;
    }
}

extern "C" void kernel_launch(void* const* d_in, const int* in_sizes, int n_in,
                              void* d_out, int out_size) {
    const float4* img  = (const float4*)d_in[0];
    const float4* proj = (const float4*)d_in[1];
    // d_in[2] = mat_reg_loss, unused by the reference computation
    const float4* org  = (const float4*)d_in[3];
    float* out = (float*)d_out;

    zero_kernel<<<1, 128>>>();
    reduce_kernel<<<BATCH * CHUNKS, THREADS>>>(img, proj, org);
    final_kernel<<<1, BATCH>>>(out);
}